// round 5
// baseline (speedup 1.0000x reference)
#include <cuda_runtime.h>
#include <math.h>

#define BTOT 262144
#define NBLK 2048

__device__ float    g_h   [(size_t)BTOT * 256];
__device__ unsigned g_enc_tf[(size_t)BTOT * 128];
__device__ float    g_s   [(size_t)BTOT * 10];
__device__ float    g_psum[256 * NBLK];
__device__ float    g_psq [256 * NBLK];
__device__ float    g_A [256];
__device__ float    g_Bb[256];
__device__ float    g_b2p[128];
__device__ unsigned g_w1hi[128 * 256], g_w1lo[128 * 256];
__device__ unsigned g_w2hi[256 * 128], g_w2lo[256 * 128];
__device__ unsigned g_we1[10 * 128 * 64];
__device__ unsigned g_w2cat[5 * 136 * 16];

__device__ __forceinline__ unsigned f2tf(float f) {
    unsigned u; asm("cvt.rna.tf32.f32 %0, %1;" : "=r"(u) : "f"(f)); return u;
}
__device__ __forceinline__ void mma8(float* c, const unsigned* a, const unsigned* b) {
    asm volatile("mma.sync.aligned.m16n8k8.row.col.f32.tf32.tf32.f32 "
        "{%0,%1,%2,%3},{%4,%5,%6,%7},{%8,%9},{%0,%1,%2,%3};"
        : "+f"(c[0]), "+f"(c[1]), "+f"(c[2]), "+f"(c[3])
        : "r"(a[0]), "r"(a[1]), "r"(a[2]), "r"(a[3]), "r"(b[0]), "r"(b[1]));
}
__device__ __forceinline__ void cpa16(void* dst, const void* src) {
    unsigned d = (unsigned)__cvta_generic_to_shared(dst);
    asm volatile("cp.async.cg.shared.global [%0],[%1],16;\n" :: "r"(d), "l"(src));
}
#define CPCOMMIT asm volatile("cp.async.commit_group;\n")
#define CPWAIT0  asm volatile("cp.async.wait_group 0;\n")
#define CPWAIT1  asm volatile("cp.async.wait_group 1;\n")

// ------------------- weight prep -------------------
__global__ void k_prep(const float* __restrict__ W1, const float* __restrict__ We1,
                       const float* __restrict__ We2, const float* __restrict__ be2) {
    int idx = blockIdx.x * blockDim.x + threadIdx.x, st = gridDim.x * blockDim.x;
    for (int i = idx; i < 128 * 256; i += st) {
        int r = i >> 8;
        float v = (r < 100) ? W1[i] : 0.f;
        unsigned h = f2tf(v);
        g_w1hi[i] = h; g_w1lo[i] = f2tf(v - __uint_as_float(h));
    }
    for (int i = idx; i < 10 * 128 * 64; i += st) g_we1[i] = f2tf(We1[i]);
    for (int i = idx; i < 5 * 136 * 16; i += st) {
        int g = i / 2176, r2 = i - g * 2176, j = r2 >> 4, a = r2 & 15;
        float v = 0.f;
        if (a < 10) {
            if (j < 128) v = We2[(size_t)((2 * g + (j >> 6)) * 64 + (j & 63)) * 10 + a];
            else if (j == 128) v = be2[(2 * g) * 10 + a];
            else if (j == 129) v = be2[(2 * g + 1) * 10 + a];
        }
        g_w2cat[i] = f2tf(v);
    }
}

// ------------------- K1: h = relu(state@W1+b1), 3xTF32, pipelined ----------
__global__ __launch_bounds__(256)
void k_gemm1(const float* __restrict__ state, const float* __restrict__ b1) {
    extern __shared__ unsigned sm[];
    unsigned* Ahi = sm;             // [128][36]
    unsigned* Alo = sm + 4608;      // buffers B: 9216 + buf*8704, hi then lo(+4352)
    const int t = threadIdx.x, w = t >> 5, lane = t & 31;
    const int gid = lane >> 2, q = lane & 3;
    const int wm = w >> 1, wn = w & 1, rowb = wm * 32, colb = wn * 64;
    const int rb = blockIdx.x, cb = blockIdx.y, row0 = rb * 128;

    float acc[2][8][4];
#pragma unroll
    for (int m = 0; m < 2; m++)
#pragma unroll
        for (int na = 0; na < 8; na++)
#pragma unroll
            for (int j = 0; j < 4; j++) acc[m][na][j] = 0.f;

    float4 a4[4];
#pragma unroll
    for (int it = 0; it < 4; it++) {
        int i4 = t + 256 * it, r = i4 >> 3, f = i4 & 7, sc = f * 4;
        a4[it] = (sc < 100) ? *(const float4*)(state + (size_t)(row0 + r) * 100 + sc)
                            : make_float4(0.f, 0.f, 0.f, 0.f);
    }
    {   // B chunk 0 -> buf0
        unsigned* Bh = sm + 9216; unsigned* Bl = Bh + 4352;
        for (int i4 = t; i4 < 1024; i4 += 256) {
            int r = i4 >> 5, c4 = i4 & 31;
            size_t gi = (size_t)r * 256 + cb * 128 + c4 * 4;
            cpa16(Bh + r * 136 + c4 * 4, g_w1hi + gi);
            cpa16(Bl + r * 136 + c4 * 4, g_w1lo + gi);
        }
        CPCOMMIT;
    }
    for (int ch = 0; ch < 4; ch++) {
        if (ch) __syncthreads();
#pragma unroll
        for (int it = 0; it < 4; it++) {
            int i4 = t + 256 * it, r = i4 >> 3, f = i4 & 7;
            unsigned h0 = f2tf(a4[it].x), h1 = f2tf(a4[it].y), h2 = f2tf(a4[it].z), h3 = f2tf(a4[it].w);
            *(uint4*)(Ahi + r * 36 + f * 4) = make_uint4(h0, h1, h2, h3);
            *(uint4*)(Alo + r * 36 + f * 4) = make_uint4(
                f2tf(a4[it].x - __uint_as_float(h0)), f2tf(a4[it].y - __uint_as_float(h1)),
                f2tf(a4[it].z - __uint_as_float(h2)), f2tf(a4[it].w - __uint_as_float(h3)));
        }
        if (ch < 3) {
            const int kk0 = (ch + 1) * 32;
            unsigned* Bh = sm + 9216 + ((ch + 1) & 1) * 8704; unsigned* Bl = Bh + 4352;
            for (int i4 = t; i4 < 1024; i4 += 256) {
                int r = i4 >> 5, c4 = i4 & 31;
                size_t gi = (size_t)(kk0 + r) * 256 + cb * 128 + c4 * 4;
                cpa16(Bh + r * 136 + c4 * 4, g_w1hi + gi);
                cpa16(Bl + r * 136 + c4 * 4, g_w1lo + gi);
            }
            CPCOMMIT;
#pragma unroll
            for (int it = 0; it < 4; it++) {
                int i4 = t + 256 * it, r = i4 >> 3, f = i4 & 7, sc = kk0 + f * 4;
                a4[it] = (sc < 100) ? *(const float4*)(state + (size_t)(row0 + r) * 100 + sc)
                                    : make_float4(0.f, 0.f, 0.f, 0.f);
            }
            CPWAIT1;
        } else { CPWAIT0; }
        __syncthreads();
        unsigned* Bh = sm + 9216 + (ch & 1) * 8704; unsigned* Bl = Bh + 4352;
#pragma unroll
        for (int ks = 0; ks < 4; ks++) {
            unsigned ah[2][4], al[2][4];
#pragma unroll
            for (int m = 0; m < 2; m++) {
                int b = (rowb + 16 * m + gid) * 36 + ks * 8 + q;
                ah[m][0] = Ahi[b]; ah[m][1] = Ahi[b + 288]; ah[m][2] = Ahi[b + 4]; ah[m][3] = Ahi[b + 292];
                al[m][0] = Alo[b]; al[m][1] = Alo[b + 288]; al[m][2] = Alo[b + 4]; al[m][3] = Alo[b + 292];
            }
#pragma unroll
            for (int na = 0; na < 8; na++) {
                int bb = (ks * 8 + q) * 136 + colb + 8 * na + gid;
                unsigned bh[2] = {Bh[bb], Bh[bb + 544]};
                unsigned bl[2] = {Bl[bb], Bl[bb + 544]};
#pragma unroll
                for (int m = 0; m < 2; m++) {
                    mma8(acc[m][na], ah[m], bh);
                    mma8(acc[m][na], al[m], bh);
                    mma8(acc[m][na], ah[m], bl);
                }
            }
        }
    }
    __syncthreads();
    float* sums = (float*)sm;     // [4][128]
    float* sqs  = sums + 512;
#pragma unroll
    for (int na = 0; na < 8; na++) {
        int cl = colb + 8 * na + 2 * q, cg = cb * 128 + cl;
        float bias0 = b1[cg], bias1 = b1[cg + 1];
        float p0 = 0.f, p1 = 0.f, q0 = 0.f, q1 = 0.f;
#pragma unroll
        for (int m = 0; m < 2; m++) {
            int r = row0 + rowb + 16 * m + gid;
            float v00 = fmaxf(acc[m][na][0] + bias0, 0.f), v01 = fmaxf(acc[m][na][1] + bias1, 0.f);
            float v10 = fmaxf(acc[m][na][2] + bias0, 0.f), v11 = fmaxf(acc[m][na][3] + bias1, 0.f);
            *(float2*)(g_h + (size_t)r * 256 + cg)       = make_float2(v00, v01);
            *(float2*)(g_h + (size_t)(r + 8) * 256 + cg) = make_float2(v10, v11);
            p0 += v00 + v10; p1 += v01 + v11;
            q0 += v00 * v00 + v10 * v10; q1 += v01 * v01 + v11 * v11;
        }
#pragma unroll
        for (int off = 4; off <= 16; off <<= 1) {
            p0 += __shfl_xor_sync(0xffffffffu, p0, off);
            p1 += __shfl_xor_sync(0xffffffffu, p1, off);
            q0 += __shfl_xor_sync(0xffffffffu, q0, off);
            q1 += __shfl_xor_sync(0xffffffffu, q1, off);
        }
        if (gid == 0) {
            sums[wm * 128 + cl] = p0; sums[wm * 128 + cl + 1] = p1;
            sqs [wm * 128 + cl] = q0; sqs [wm * 128 + cl + 1] = q1;
        }
    }
    __syncthreads();
    if (t < 128) {
        float S = sums[t] + sums[128 + t] + sums[256 + t] + sums[384 + t];
        float Q = sqs[t] + sqs[128 + t] + sqs[256 + t] + sqs[384 + t];
        g_psum[(cb * 128 + t) * NBLK + rb] = S;
        g_psq [(cb * 128 + t) * NBLK + rb] = Q;
    }
}

// ------------------- K2: BN stats finalize -------------------
__global__ __launch_bounds__(256)
void k_stats(const float* __restrict__ gamma, const float* __restrict__ beta) {
    const int c = blockIdx.x, t = threadIdx.x;
    float s = 0.f, qq = 0.f;
    for (int i = t; i < NBLK; i += 256) { s += g_psum[c * NBLK + i]; qq += g_psq[c * NBLK + i]; }
#pragma unroll
    for (int off = 16; off; off >>= 1) {
        s += __shfl_xor_sync(0xffffffffu, s, off);
        qq += __shfl_xor_sync(0xffffffffu, qq, off);
    }
    __shared__ float ss[8], sq[8];
    if ((t & 31) == 0) { ss[t >> 5] = s; sq[t >> 5] = qq; }
    __syncthreads();
    if (t == 0) {
        float S = 0.f, Q = 0.f;
#pragma unroll
        for (int wv = 0; wv < 8; wv++) { S += ss[wv]; Q += sq[wv]; }
        const float inv_n = 1.f / (float)BTOT;
        float mu = S * inv_n;
        float var = Q * inv_n - mu * mu;
        float rstd = rsqrtf(var + 1e-5f);
        float gg = gamma[c];
        g_A[c] = rstd * gg;
        g_Bb[c] = beta[c] - mu * rstd * gg;
    }
}

// ------------------- K2b: fold BN affine into W2 + b2 -------------------
__global__ __launch_bounds__(256)
void k_fold(const float* __restrict__ W2, const float* __restrict__ b2) {
    const int j = blockIdx.x, t = threadIdx.x;   // t = channel c
    float wv = W2[t * 128 + j];
    float sc = g_A[t] * wv;
    unsigned h = f2tf(sc);
    g_w2hi[t * 128 + j] = h;
    g_w2lo[t * 128 + j] = f2tf(sc - __uint_as_float(h));
    float p = g_Bb[t] * wv;
#pragma unroll
    for (int off = 16; off; off >>= 1) p += __shfl_xor_sync(0xffffffffu, p, off);
    __shared__ float red[8];
    if ((t & 31) == 0) red[t >> 5] = p;
    __syncthreads();
    if (t == 0) {
        float S = 0.f;
#pragma unroll
        for (int i = 0; i < 8; i++) S += red[i];
        g_b2p[j] = b2[j] + S;
    }
}

// ------- K3: enc = tanh(h@W2'+b2'), 3xTF32, pipelined, + fused softmax -----
__global__ __launch_bounds__(256)
void k_gemm2(const float* __restrict__ att) {
    extern __shared__ unsigned sm[];
    unsigned* Ahi = sm;
    unsigned* Alo = sm + 4608;
    float* attS = (float*)(sm + 26624);   // [10][128], end 27904
    const int t = threadIdx.x, w = t >> 5, lane = t & 31;
    const int gid = lane >> 2, q = lane & 3;
    const int wm = w >> 1, wn = w & 1, rowb = wm * 32, colb = wn * 64;
    const int row0 = blockIdx.x * 128;

    for (int i = t; i < 1280; i += 256) attS[i] = att[i];

    float acc[2][8][4];
#pragma unroll
    for (int m = 0; m < 2; m++)
#pragma unroll
        for (int na = 0; na < 8; na++)
#pragma unroll
            for (int j = 0; j < 4; j++) acc[m][na][j] = 0.f;

    float4 a4[4];
#pragma unroll
    for (int it = 0; it < 4; it++) {
        int i4 = t + 256 * it, r = i4 >> 3, f = i4 & 7;
        a4[it] = *(const float4*)(g_h + (size_t)(row0 + r) * 256 + f * 4);
    }
    {
        unsigned* Bh = sm + 9216; unsigned* Bl = Bh + 4352;
        for (int i4 = t; i4 < 1024; i4 += 256) {
            int r = i4 >> 5, c4 = i4 & 31;
            size_t gi = (size_t)r * 128 + c4 * 4;
            cpa16(Bh + r * 136 + c4 * 4, g_w2hi + gi);
            cpa16(Bl + r * 136 + c4 * 4, g_w2lo + gi);
        }
        CPCOMMIT;
    }
    for (int ch = 0; ch < 8; ch++) {
        if (ch) __syncthreads();
#pragma unroll
        for (int it = 0; it < 4; it++) {
            int i4 = t + 256 * it, r = i4 >> 3, f = i4 & 7;
            unsigned h0 = f2tf(a4[it].x), h1 = f2tf(a4[it].y), h2 = f2tf(a4[it].z), h3 = f2tf(a4[it].w);
            *(uint4*)(Ahi + r * 36 + f * 4) = make_uint4(h0, h1, h2, h3);
            *(uint4*)(Alo + r * 36 + f * 4) = make_uint4(
                f2tf(a4[it].x - __uint_as_float(h0)), f2tf(a4[it].y - __uint_as_float(h1)),
                f2tf(a4[it].z - __uint_as_float(h2)), f2tf(a4[it].w - __uint_as_float(h3)));
        }
        if (ch < 7) {
            const int kk0 = (ch + 1) * 32;
            unsigned* Bh = sm + 9216 + ((ch + 1) & 1) * 8704; unsigned* Bl = Bh + 4352;
            for (int i4 = t; i4 < 1024; i4 += 256) {
                int r = i4 >> 5, c4 = i4 & 31;
                size_t gi = (size_t)(kk0 + r) * 128 + c4 * 4;
                cpa16(Bh + r * 136 + c4 * 4, g_w2hi + gi);
                cpa16(Bl + r * 136 + c4 * 4, g_w2lo + gi);
            }
            CPCOMMIT;
#pragma unroll
            for (int it = 0; it < 4; it++) {
                int i4 = t + 256 * it, r = i4 >> 3, f = i4 & 7;
                a4[it] = *(const float4*)(g_h + (size_t)(row0 + r) * 256 + kk0 + f * 4);
            }
            CPWAIT1;
        } else { CPWAIT0; }
        __syncthreads();
        unsigned* Bh = sm + 9216 + (ch & 1) * 8704; unsigned* Bl = Bh + 4352;
#pragma unroll
        for (int ks = 0; ks < 4; ks++) {
            unsigned ah[2][4], al[2][4];
#pragma unroll
            for (int m = 0; m < 2; m++) {
                int b = (rowb + 16 * m + gid) * 36 + ks * 8 + q;
                ah[m][0] = Ahi[b]; ah[m][1] = Ahi[b + 288]; ah[m][2] = Ahi[b + 4]; ah[m][3] = Ahi[b + 292];
                al[m][0] = Alo[b]; al[m][1] = Alo[b + 288]; al[m][2] = Alo[b + 4]; al[m][3] = Alo[b + 292];
            }
#pragma unroll
            for (int na = 0; na < 8; na++) {
                int bb = (ks * 8 + q) * 136 + colb + 8 * na + gid;
                unsigned bh[2] = {Bh[bb], Bh[bb + 544]};
                unsigned bl[2] = {Bl[bb], Bl[bb + 544]};
#pragma unroll
                for (int m = 0; m < 2; m++) {
                    mma8(acc[m][na], ah[m], bh);
                    mma8(acc[m][na], al[m], bh);
                    mma8(acc[m][na], ah[m], bl);
                }
            }
        }
    }
    // epilogue: enc -> smem(fp32) + gmem(tf32); then distances + softmax
    __syncthreads();
    float* encS = (float*)sm;   // [128][132]
#pragma unroll
    for (int na = 0; na < 8; na++) {
        int cl = colb + 8 * na + 2 * q;
        float bb0 = g_b2p[cl], bb1 = g_b2p[cl + 1];
#pragma unroll
        for (int m = 0; m < 2; m++) {
            int r = rowb + 16 * m + gid;
            float e00 = tanhf(acc[m][na][0] + bb0), e01 = tanhf(acc[m][na][1] + bb1);
            float e10 = tanhf(acc[m][na][2] + bb0), e11 = tanhf(acc[m][na][3] + bb1);
            encS[r * 132 + cl] = e00;       encS[r * 132 + cl + 1] = e01;
            encS[(r + 8) * 132 + cl] = e10; encS[(r + 8) * 132 + cl + 1] = e11;
            *(uint2*)(g_enc_tf + (size_t)(row0 + r) * 128 + cl)     = make_uint2(f2tf(e00), f2tf(e01));
            *(uint2*)(g_enc_tf + (size_t)(row0 + r + 8) * 128 + cl) = make_uint2(f2tf(e10), f2tf(e11));
        }
    }
    __syncthreads();
    for (int it = 0; it < 16; it++) {
        int r = w * 16 + it;
        float4 e4 = *(float4*)(encS + r * 132 + lane * 4);
        float d[10];
#pragma unroll
        for (int k = 0; k < 10; k++) {
            float4 aa = *(float4*)(attS + k * 128 + lane * 4);
            float dx = e4.x - aa.x, dy = e4.y - aa.y, dz = e4.z - aa.z, dw = e4.w - aa.w;
            float p = dx * dx + dy * dy + dz * dz + dw * dw;
#pragma unroll
            for (int off = 16; off; off >>= 1) p += __shfl_xor_sync(0xffffffffu, p, off);
            d[k] = sqrtf(p);
        }
        float dmin = d[0];
#pragma unroll
        for (int k = 1; k < 10; k++) dmin = fminf(dmin, d[k]);
        float s[10], Z = 0.f;
#pragma unroll
        for (int k = 0; k < 10; k++) { s[k] = expf(-2.f * (d[k] - dmin)); Z += s[k]; }
        float invZ = 1.f / Z;
#pragma unroll
        for (int k = 0; k < 10; k++)
            if (lane == k) g_s[(size_t)(row0 + r) * 10 + k] = s[k] * invZ;
    }
}

// ------------- K4: fused experts + gated contraction (512 thr) -------------
__global__ __launch_bounds__(512)
void k_fused(const float* __restrict__ be1, float* __restrict__ out) {
    extern __shared__ unsigned sm[];
    unsigned* Ae   = sm;                 // enc tf32 [128][132]
    unsigned* buf2 = sm + 16896;         // We1 [128][136] / ehs [128][140]
    unsigned* B2   = sm + 34816;         // [136][16]
    float* sS  = (float*)(sm + 36992);   // [128][12]
    float* sBe = (float*)(sm + 38528);   // [128]; total 38656 words
    const int t = threadIdx.x, w = t >> 5, lane = t & 31;
    const int gid = lane >> 2, q = lane & 3;
    const int wm = w >> 2, wn = w & 3;
    const int row0 = blockIdx.x * 128;

    for (int i4 = t; i4 < 4096; i4 += 512) {
        int r = i4 >> 5, c4 = i4 & 31;
        cpa16(Ae + r * 132 + c4 * 4, g_enc_tf + (size_t)(row0 + r) * 128 + c4 * 4);
    }
    CPCOMMIT;
    for (int i = t; i < 1280; i += 512) {
        int r = i / 10, k = i - r * 10;
        sS[r * 12 + k] = g_s[(size_t)(row0 + r) * 10 + k];
    }

    float acc2[2][4];
#pragma unroll
    for (int nf = 0; nf < 2; nf++)
#pragma unroll
        for (int j = 0; j < 4; j++) acc2[nf][j] = 0.f;

    for (int g = 0; g < 5; g++) {
        __syncthreads();
        for (int i4 = t; i4 < 4096; i4 += 512) {
            int e = i4 >> 5, j4 = i4 & 31;
            cpa16(buf2 + e * 136 + j4 * 4,
                  g_we1 + ((size_t)(2 * g + (j4 >> 4)) * 128 + e) * 64 + (j4 & 15) * 4);
        }
        CPCOMMIT;
        if (t < 128) sBe[t] = be1[g * 128 + t];
        for (int i = t; i < 544; i += 512)
            ((uint4*)B2)[i] = ((const uint4*)(g_w2cat + g * 2176))[i];
        CPWAIT0;
        __syncthreads();

        float acc[2][4][4];
#pragma unroll
        for (int m = 0; m < 2; m++)
#pragma unroll
            for (int na = 0; na < 4; na++)
#pragma unroll
                for (int j = 0; j < 4; j++) acc[m][na][j] = 0.f;
#pragma unroll
        for (int ks = 0; ks < 16; ks++) {
            unsigned a[2][4];
#pragma unroll
            for (int m = 0; m < 2; m++) {
                int b = (wm * 32 + 16 * m + gid) * 132 + ks * 8 + q;
                a[m][0] = Ae[b]; a[m][1] = Ae[b + 1056]; a[m][2] = Ae[b + 4]; a[m][3] = Ae[b + 1060];
            }
#pragma unroll
            for (int na = 0; na < 4; na++) {
                int bb = (ks * 8 + q) * 136 + wn * 32 + 8 * na + gid;
                unsigned bh[2] = {buf2[bb], buf2[bb + 544]};
                mma8(acc[0][na], a[0], bh);
                mma8(acc[1][na], a[1], bh);
            }
        }
        __syncthreads();
#pragma unroll
        for (int na = 0; na < 4; na++) {
            int jc = wn * 32 + 8 * na + 2 * q;
            float bia0 = sBe[jc], bia1 = sBe[jc + 1];
            int k0 = 2 * g + (jc >> 6);
#pragma unroll
            for (int m = 0; m < 2; m++) {
                int rr = wm * 32 + 16 * m + gid;
                float s0 = sS[rr * 12 + k0], s1 = sS[(rr + 8) * 12 + k0];
                buf2[rr * 140 + jc]           = f2tf(fmaxf(acc[m][na][0] + bia0, 0.f) * s0);
                buf2[rr * 140 + jc + 1]       = f2tf(fmaxf(acc[m][na][1] + bia1, 0.f) * s0);
                buf2[(rr + 8) * 140 + jc]     = f2tf(fmaxf(acc[m][na][2] + bia0, 0.f) * s1);
                buf2[(rr + 8) * 140 + jc + 1] = f2tf(fmaxf(acc[m][na][3] + bia1, 0.f) * s1);
            }
        }
        for (int i = t; i < 1024; i += 512) {
            int r = i >> 3, jj = 128 + (i & 7);
            float v = (jj == 128) ? sS[r * 12 + 2 * g] : ((jj == 129) ? sS[r * 12 + 2 * g + 1] : 0.f);
            buf2[r * 140 + jj] = f2tf(v);
        }
        __syncthreads();
        if (w < 8) {
#pragma unroll
            for (int ks = 0; ks < 17; ks++) {
                int b = (w * 16 + gid) * 140 + ks * 8 + q;
                unsigned a2[4] = {buf2[b], buf2[b + 1120], buf2[b + 4], buf2[b + 1124]};
#pragma unroll
                for (int nf = 0; nf < 2; nf++) {
                    int bb = (ks * 8 + q) * 16 + nf * 8 + gid;
                    unsigned bh[2] = {B2[bb], B2[bb + 64]};
                    mma8(acc2[nf], a2, bh);
                }
            }
        }
    }
    if (w < 8) {
        size_t r = row0 + w * 16 + gid;
        out[r * 10 + 2 * q]           = acc2[0][0];
        out[r * 10 + 2 * q + 1]       = acc2[0][1];
        out[(r + 8) * 10 + 2 * q]     = acc2[0][2];
        out[(r + 8) * 10 + 2 * q + 1] = acc2[0][3];
        if (q == 0) {
            out[r * 10 + 8] = acc2[1][0];       out[r * 10 + 9] = acc2[1][1];
            out[(r + 8) * 10 + 8] = acc2[1][2]; out[(r + 8) * 10 + 9] = acc2[1][3];
        }
    }
}

// ---------------------------------------------------------------------------
extern "C" void kernel_launch(void* const* d_in, const int* in_sizes, int n_in,
                              void* d_out, int out_size) {
    const float* state = (const float*)d_in[0];
    const float* W1    = (const float*)d_in[1];
    const float* b1    = (const float*)d_in[2];
    const float* gamma = (const float*)d_in[3];
    const float* beta  = (const float*)d_in[4];
    const float* W2    = (const float*)d_in[5];
    const float* b2    = (const float*)d_in[6];
    const float* We1   = (const float*)d_in[7];
    const float* be1   = (const float*)d_in[8];
    const float* We2   = (const float*)d_in[9];
    const float* be2   = (const float*)d_in[10];
    const float* att   = (const float*)d_in[11];
    float* out = (float*)d_out;

    const int SM1 = 26624 * 4, SM2 = 27904 * 4, SMF = 38656 * 4;
    cudaFuncSetAttribute(k_gemm1, cudaFuncAttributeMaxDynamicSharedMemorySize, SM1);
    cudaFuncSetAttribute(k_gemm2, cudaFuncAttributeMaxDynamicSharedMemorySize, SM2);
    cudaFuncSetAttribute(k_fused, cudaFuncAttributeMaxDynamicSharedMemorySize, SMF);

    k_prep <<<256, 256>>>(W1, We1, We2, be2);
    k_gemm1<<<dim3(NBLK, 2), 256, SM1>>>(state, b1);
    k_stats<<<256, 256>>>(gamma, beta);
    k_fold <<<128, 256>>>(W2, b2);
    k_gemm2<<<NBLK, 256, SM2>>>(att);
    k_fused<<<NBLK, 512, SMF>>>(be1, out);
}

// round 6
// speedup vs baseline: 1.3290x; 1.3290x over previous
#include <cuda_runtime.h>
#include <cuda_bf16.h>
#include <math.h>

#define BTOT 262144
#define NBLK 2048

__device__ float    g_h   [(size_t)BTOT * 256];
__device__ unsigned g_enc_tf[(size_t)BTOT * 128];
__device__ float    g_s   [(size_t)BTOT * 10];
__device__ float    g_psum[256 * NBLK];
__device__ float    g_psq [256 * NBLK];
__device__ float    g_A [256];
__device__ float    g_Bb[256];
__device__ float    g_b2p[128];
__device__ unsigned short g_w1h[256 * 128], g_w1l[256 * 128];  // [n][k] pairs, k pad 128
__device__ unsigned short g_w2h[128 * 256], g_w2l[128 * 256];  // [n][k] folded W2'
__device__ unsigned g_we1[10 * 128 * 64];                      // tf32
__device__ unsigned g_w2cat[5 * 136 * 16];                     // tf32

__device__ __forceinline__ unsigned f2tf(float f) {
    unsigned u; asm("cvt.rna.tf32.f32 %0, %1;" : "=r"(u) : "f"(f)); return u;
}
__device__ __forceinline__ void mma8(float* c, const unsigned* a, const unsigned* b) {
    asm volatile("mma.sync.aligned.m16n8k8.row.col.f32.tf32.tf32.f32 "
        "{%0,%1,%2,%3},{%4,%5,%6,%7},{%8,%9},{%0,%1,%2,%3};"
        : "+f"(c[0]), "+f"(c[1]), "+f"(c[2]), "+f"(c[3])
        : "r"(a[0]), "r"(a[1]), "r"(a[2]), "r"(a[3]), "r"(b[0]), "r"(b[1]));
}
__device__ __forceinline__ void mma16(float* c, const unsigned* a, const unsigned* b) {
    asm volatile("mma.sync.aligned.m16n8k16.row.col.f32.bf16.bf16.f32 "
        "{%0,%1,%2,%3},{%4,%5,%6,%7},{%8,%9},{%0,%1,%2,%3};"
        : "+f"(c[0]), "+f"(c[1]), "+f"(c[2]), "+f"(c[3])
        : "r"(a[0]), "r"(a[1]), "r"(a[2]), "r"(a[3]), "r"(b[0]), "r"(b[1]));
}
__device__ __forceinline__ unsigned short bh16(float v) {
    __nv_bfloat16 b = __float2bfloat16(v); return *(unsigned short*)&b;
}
__device__ __forceinline__ float bup(unsigned short u) {
    __nv_bfloat16 b = *(__nv_bfloat16*)&u; return __bfloat162float(b);
}
__device__ __forceinline__ void packpair(float v0, float v1, unsigned& hp, unsigned& lp) {
    unsigned short h0 = bh16(v0), h1 = bh16(v1);
    hp = (unsigned)h0 | ((unsigned)h1 << 16);
    lp = (unsigned)bh16(v0 - bup(h0)) | ((unsigned)bh16(v1 - bup(h1)) << 16);
}
__device__ __forceinline__ void cpa16(void* dst, const void* src) {
    unsigned d = (unsigned)__cvta_generic_to_shared(dst);
    asm volatile("cp.async.cg.shared.global [%0],[%1],16;\n" :: "r"(d), "l"(src));
}
#define CPCOMMIT asm volatile("cp.async.commit_group;\n")
#define CPWAIT0  asm volatile("cp.async.wait_group 0;\n")

// ------------------- prep: W1 bf16 image + tf32 expert weights -------------
__global__ void k_prep(const float* __restrict__ W1, const float* __restrict__ We1,
                       const float* __restrict__ We2, const float* __restrict__ be2) {
    int idx = blockIdx.x * blockDim.x + threadIdx.x, st = gridDim.x * blockDim.x;
    for (int i = idx; i < 256 * 128; i += st) {
        int n = i >> 7, k = i & 127;
        float v = (k < 100) ? W1[k * 256 + n] : 0.f;
        unsigned short h = bh16(v);
        g_w1h[i] = h; g_w1l[i] = bh16(v - bup(h));
    }
    for (int i = idx; i < 10 * 128 * 64; i += st) g_we1[i] = f2tf(We1[i]);
    for (int i = idx; i < 5 * 136 * 16; i += st) {
        int g = i / 2176, r2 = i - g * 2176, j = r2 >> 4, a = r2 & 15;
        float v = 0.f;
        if (a < 10) {
            if (j < 128) v = We2[(size_t)((2 * g + (j >> 6)) * 64 + (j & 63)) * 10 + a];
            else if (j == 128) v = be2[(2 * g) * 10 + a];
            else if (j == 129) v = be2[(2 * g + 1) * 10 + a];
        }
        g_w2cat[i] = f2tf(v);
    }
}

// ------- K1: h = relu(state@W1+b1), bf16 3-term, 512 thr, full N=256 -------
__global__ __launch_bounds__(512)
void k_gemm1(const float* __restrict__ state, const float* __restrict__ b1) {
    extern __shared__ unsigned sm[];
    unsigned* Ahi = sm;              // [128][68] pair-words (K=128 -> 64 pw)
    unsigned* Alo = sm + 8704;
    unsigned* Bhi = sm + 17408;      // [256][68]
    unsigned* Blo = sm + 34816;      // end 52224 words
    const int t = threadIdx.x, w = t >> 5, lane = t & 31;
    const int gid = lane >> 2, q = lane & 3;
    const int wm = w >> 2, wn = w & 3, rowb = wm * 32, colb = wn * 64;
    const size_t row0 = (size_t)blockIdx.x * 128;

    for (int i = t; i < 1024; i += 512) {
        int r = i >> 3, sl = i & 7, c0 = sl * 16;
        float vv[16];
#pragma unroll
        for (int u = 0; u < 4; u++) {
            int k = c0 + u * 4;
            float4 x = (k < 100) ? *(const float4*)(state + (row0 + r) * 100 + k)
                                 : make_float4(0.f, 0.f, 0.f, 0.f);
            vv[4 * u] = x.x; vv[4 * u + 1] = x.y; vv[4 * u + 2] = x.z; vv[4 * u + 3] = x.w;
        }
        unsigned H[8], L[8];
#pragma unroll
        for (int u = 0; u < 8; u++) packpair(vv[2 * u], vv[2 * u + 1], H[u], L[u]);
        *(uint4*)(Ahi + r * 68 + sl * 8)     = make_uint4(H[0], H[1], H[2], H[3]);
        *(uint4*)(Ahi + r * 68 + sl * 8 + 4) = make_uint4(H[4], H[5], H[6], H[7]);
        *(uint4*)(Alo + r * 68 + sl * 8)     = make_uint4(L[0], L[1], L[2], L[3]);
        *(uint4*)(Alo + r * 68 + sl * 8 + 4) = make_uint4(L[4], L[5], L[6], L[7]);
    }
    {
        const unsigned* w1hw = (const unsigned*)g_w1h;
        const unsigned* w1lw = (const unsigned*)g_w1l;
        for (int i = t; i < 4096; i += 512) {
            int n = i >> 4, c4 = i & 15;
            *(uint4*)(Bhi + n * 68 + c4 * 4) = *(const uint4*)(w1hw + n * 64 + c4 * 4);
            *(uint4*)(Blo + n * 68 + c4 * 4) = *(const uint4*)(w1lw + n * 64 + c4 * 4);
        }
    }
    __syncthreads();

    float acc[2][8][4];
#pragma unroll
    for (int m = 0; m < 2; m++)
#pragma unroll
        for (int na = 0; na < 8; na++)
#pragma unroll
            for (int j = 0; j < 4; j++) acc[m][na][j] = 0.f;
#pragma unroll
    for (int ks = 0; ks < 8; ks++) {
        unsigned ah[2][4], al[2][4];
#pragma unroll
        for (int m = 0; m < 2; m++) {
            int b = (rowb + 16 * m + gid) * 68 + ks * 8 + q;
            ah[m][0] = Ahi[b]; ah[m][1] = Ahi[b + 544]; ah[m][2] = Ahi[b + 4]; ah[m][3] = Ahi[b + 548];
            al[m][0] = Alo[b]; al[m][1] = Alo[b + 544]; al[m][2] = Alo[b + 4]; al[m][3] = Alo[b + 548];
        }
#pragma unroll
        for (int na = 0; na < 8; na++) {
            int bb = (colb + 8 * na + gid) * 68 + ks * 8 + q;
            unsigned bh[2] = {Bhi[bb], Bhi[bb + 4]};
            unsigned bl[2] = {Blo[bb], Blo[bb + 4]};
#pragma unroll
            for (int m = 0; m < 2; m++) {
                mma16(acc[m][na], ah[m], bh);
                mma16(acc[m][na], al[m], bh);
                mma16(acc[m][na], ah[m], bl);
            }
        }
    }
    __syncthreads();
    float* sums = (float*)sm;     // [4][256]
    float* sqs  = sums + 1024;
#pragma unroll
    for (int na = 0; na < 8; na++) {
        int cg = colb + 8 * na + 2 * q;
        float bias0 = b1[cg], bias1 = b1[cg + 1];
        float p0 = 0.f, p1 = 0.f, q0 = 0.f, q1 = 0.f;
#pragma unroll
        for (int m = 0; m < 2; m++) {
            size_t r = row0 + rowb + 16 * m + gid;
            float v00 = fmaxf(acc[m][na][0] + bias0, 0.f), v01 = fmaxf(acc[m][na][1] + bias1, 0.f);
            float v10 = fmaxf(acc[m][na][2] + bias0, 0.f), v11 = fmaxf(acc[m][na][3] + bias1, 0.f);
            *(float2*)(g_h + r * 256 + cg)       = make_float2(v00, v01);
            *(float2*)(g_h + (r + 8) * 256 + cg) = make_float2(v10, v11);
            p0 += v00 + v10; p1 += v01 + v11;
            q0 += v00 * v00 + v10 * v10; q1 += v01 * v01 + v11 * v11;
        }
#pragma unroll
        for (int off = 4; off <= 16; off <<= 1) {
            p0 += __shfl_xor_sync(0xffffffffu, p0, off);
            p1 += __shfl_xor_sync(0xffffffffu, p1, off);
            q0 += __shfl_xor_sync(0xffffffffu, q0, off);
            q1 += __shfl_xor_sync(0xffffffffu, q1, off);
        }
        if (gid == 0) {
            sums[wm * 256 + cg] = p0; sums[wm * 256 + cg + 1] = p1;
            sqs [wm * 256 + cg] = q0; sqs [wm * 256 + cg + 1] = q1;
        }
    }
    __syncthreads();
    if (t < 256) {
        float S = sums[t] + sums[256 + t] + sums[512 + t] + sums[768 + t];
        float Q = sqs[t] + sqs[256 + t] + sqs[512 + t] + sqs[768 + t];
        g_psum[t * NBLK + blockIdx.x] = S;
        g_psq [t * NBLK + blockIdx.x] = Q;
    }
}

// ------------------- K2: BN stats finalize -------------------
__global__ __launch_bounds__(256)
void k_stats(const float* __restrict__ gamma, const float* __restrict__ beta) {
    const int c = blockIdx.x, t = threadIdx.x;
    float s = 0.f, qq = 0.f;
    for (int i = t; i < NBLK; i += 256) { s += g_psum[c * NBLK + i]; qq += g_psq[c * NBLK + i]; }
#pragma unroll
    for (int off = 16; off; off >>= 1) {
        s += __shfl_xor_sync(0xffffffffu, s, off);
        qq += __shfl_xor_sync(0xffffffffu, qq, off);
    }
    __shared__ float ss[8], sq[8];
    if ((t & 31) == 0) { ss[t >> 5] = s; sq[t >> 5] = qq; }
    __syncthreads();
    if (t == 0) {
        float S = 0.f, Q = 0.f;
#pragma unroll
        for (int wv = 0; wv < 8; wv++) { S += ss[wv]; Q += sq[wv]; }
        const float inv_n = 1.f / (float)BTOT;
        float mu = S * inv_n;
        float var = Q * inv_n - mu * mu;
        float rstd = rsqrtf(var + 1e-5f);
        float gg = gamma[c];
        g_A[c] = rstd * gg;
        g_Bb[c] = beta[c] - mu * rstd * gg;
    }
}

// ------------- K2b: fold BN into W2 (bf16 split image) + b2' ---------------
__global__ __launch_bounds__(256)
void k_fold(const float* __restrict__ W2, const float* __restrict__ b2) {
    const int n = blockIdx.x, k = threadIdx.x;
    float sc = g_A[k] * W2[k * 128 + n];
    unsigned short h = bh16(sc);
    g_w2h[n * 256 + k] = h;
    g_w2l[n * 256 + k] = bh16(sc - bup(h));
    float p = g_Bb[k] * W2[k * 128 + n];
#pragma unroll
    for (int off = 16; off; off >>= 1) p += __shfl_xor_sync(0xffffffffu, p, off);
    __shared__ float red[8];
    if ((k & 31) == 0) red[k >> 5] = p;
    __syncthreads();
    if (k == 0) {
        float S = 0.f;
#pragma unroll
        for (int i = 0; i < 8; i++) S += red[i];
        g_b2p[n] = b2[n] + S;
    }
}

// -- K3: enc = tanh(h@W2'+b2'), bf16 3-term, 2 K-chunks, fused softmax ------
__global__ __launch_bounds__(512)
void k_gemm2(const float* __restrict__ att) {
    extern __shared__ unsigned sm[];
    unsigned* Ahi = sm;              // [128][68]
    unsigned* Alo = sm + 8704;
    unsigned* Bhi = sm + 17408;      // [128][68]
    unsigned* Blo = sm + 26112;      // end 34816
    float* attS = (float*)(sm + 34816);   // [10][128]
    float* b2ps = (float*)(sm + 36096);   // [128], end 36224 words
    const int t = threadIdx.x, w = t >> 5, lane = t & 31;
    const int gid = lane >> 2, q = lane & 3;
    const int wm = w >> 2, wn = w & 3, rowb = wm * 32, colb = wn * 32;
    const size_t row0 = (size_t)blockIdx.x * 128;

    for (int i = t; i < 1280; i += 512) attS[i] = att[i];
    if (t < 128) b2ps[t] = g_b2p[t];

    float acc[2][4][4];
#pragma unroll
    for (int m = 0; m < 2; m++)
#pragma unroll
        for (int na = 0; na < 4; na++)
#pragma unroll
            for (int j = 0; j < 4; j++) acc[m][na][j] = 0.f;

    const unsigned* w2hw = (const unsigned*)g_w2h;
    const unsigned* w2lw = (const unsigned*)g_w2l;
    for (int kc = 0; kc < 2; kc++) {
        __syncthreads();
        for (int i = t; i < 1024; i += 512) {
            int r = i >> 3, sl = i & 7;
            const float* hp = g_h + (row0 + r) * 256 + kc * 128 + sl * 16;
            float4 x0 = *(const float4*)hp,       x1 = *(const float4*)(hp + 4);
            float4 x2 = *(const float4*)(hp + 8), x3 = *(const float4*)(hp + 12);
            unsigned H[8], L[8];
            packpair(x0.x, x0.y, H[0], L[0]); packpair(x0.z, x0.w, H[1], L[1]);
            packpair(x1.x, x1.y, H[2], L[2]); packpair(x1.z, x1.w, H[3], L[3]);
            packpair(x2.x, x2.y, H[4], L[4]); packpair(x2.z, x2.w, H[5], L[5]);
            packpair(x3.x, x3.y, H[6], L[6]); packpair(x3.z, x3.w, H[7], L[7]);
            *(uint4*)(Ahi + r * 68 + sl * 8)     = make_uint4(H[0], H[1], H[2], H[3]);
            *(uint4*)(Ahi + r * 68 + sl * 8 + 4) = make_uint4(H[4], H[5], H[6], H[7]);
            *(uint4*)(Alo + r * 68 + sl * 8)     = make_uint4(L[0], L[1], L[2], L[3]);
            *(uint4*)(Alo + r * 68 + sl * 8 + 4) = make_uint4(L[4], L[5], L[6], L[7]);
        }
        for (int i = t; i < 2048; i += 512) {
            int n = i >> 4, c4 = i & 15;
            *(uint4*)(Bhi + n * 68 + c4 * 4) = *(const uint4*)(w2hw + n * 128 + kc * 64 + c4 * 4);
            *(uint4*)(Blo + n * 68 + c4 * 4) = *(const uint4*)(w2lw + n * 128 + kc * 64 + c4 * 4);
        }
        __syncthreads();
#pragma unroll
        for (int ks = 0; ks < 8; ks++) {
            unsigned ah[2][4], al[2][4];
#pragma unroll
            for (int m = 0; m < 2; m++) {
                int b = (rowb + 16 * m + gid) * 68 + ks * 8 + q;
                ah[m][0] = Ahi[b]; ah[m][1] = Ahi[b + 544]; ah[m][2] = Ahi[b + 4]; ah[m][3] = Ahi[b + 548];
                al[m][0] = Alo[b]; al[m][1] = Alo[b + 544]; al[m][2] = Alo[b + 4]; al[m][3] = Alo[b + 548];
            }
#pragma unroll
            for (int na = 0; na < 4; na++) {
                int bb = (colb + 8 * na + gid) * 68 + ks * 8 + q;
                unsigned bh[2] = {Bhi[bb], Bhi[bb + 4]};
                unsigned bl[2] = {Blo[bb], Blo[bb + 4]};
#pragma unroll
                for (int m = 0; m < 2; m++) {
                    mma16(acc[m][na], ah[m], bh);
                    mma16(acc[m][na], al[m], bh);
                    mma16(acc[m][na], ah[m], bl);
                }
            }
        }
    }
    // epilogue: tanh -> encS(smem) + g_enc_tf; distances + softmax
    __syncthreads();
    float* encS = (float*)sm;   // [128][132]
#pragma unroll
    for (int na = 0; na < 4; na++) {
        int cl = colb + 8 * na + 2 * q;
        float bb0 = b2ps[cl], bb1 = b2ps[cl + 1];
#pragma unroll
        for (int m = 0; m < 2; m++) {
            int r = rowb + 16 * m + gid;
            float e00 = tanhf(acc[m][na][0] + bb0), e01 = tanhf(acc[m][na][1] + bb1);
            float e10 = tanhf(acc[m][na][2] + bb0), e11 = tanhf(acc[m][na][3] + bb1);
            encS[r * 132 + cl] = e00;       encS[r * 132 + cl + 1] = e01;
            encS[(r + 8) * 132 + cl] = e10; encS[(r + 8) * 132 + cl + 1] = e11;
            *(uint2*)(g_enc_tf + (row0 + r) * 128 + cl)     = make_uint2(f2tf(e00), f2tf(e01));
            *(uint2*)(g_enc_tf + (row0 + r + 8) * 128 + cl) = make_uint2(f2tf(e10), f2tf(e11));
        }
    }
    __syncthreads();
    for (int it = 0; it < 8; it++) {
        int r = w * 8 + it;
        float4 e4 = *(float4*)(encS + r * 132 + lane * 4);
        float d[10];
#pragma unroll
        for (int k = 0; k < 10; k++) {
            float4 aa = *(float4*)(attS + k * 128 + lane * 4);
            float dx = e4.x - aa.x, dy = e4.y - aa.y, dz = e4.z - aa.z, dw = e4.w - aa.w;
            float p = dx * dx + dy * dy + dz * dz + dw * dw;
#pragma unroll
            for (int off = 16; off; off >>= 1) p += __shfl_xor_sync(0xffffffffu, p, off);
            d[k] = sqrtf(p);
        }
        float dmin = d[0];
#pragma unroll
        for (int k = 1; k < 10; k++) dmin = fminf(dmin, d[k]);
        float s[10], Z = 0.f;
#pragma unroll
        for (int k = 0; k < 10; k++) { s[k] = expf(-2.f * (d[k] - dmin)); Z += s[k]; }
        float invZ = 1.f / Z;
#pragma unroll
        for (int k = 0; k < 10; k++)
            if (lane == k) g_s[(row0 + r) * 10 + k] = s[k] * invZ;
    }
}

// ------------- K4: fused experts + gated contraction (512 thr) -------------
__global__ __launch_bounds__(512)
void k_fused(const float* __restrict__ be1, float* __restrict__ out) {
    extern __shared__ unsigned sm[];
    unsigned* Ae   = sm;                 // enc tf32 [128][132]
    unsigned* buf2 = sm + 16896;         // We1 [128][136] / ehs [128][140]
    unsigned* B2   = sm + 34816;         // [136][16]
    float* sS  = (float*)(sm + 36992);   // [128][12]
    float* sBe = (float*)(sm + 38528);   // [128]; total 38656 words
    const int t = threadIdx.x, w = t >> 5, lane = t & 31;
    const int gid = lane >> 2, q = lane & 3;
    const int wm = w >> 2, wn = w & 3;
    const int row0 = blockIdx.x * 128;

    for (int i4 = t; i4 < 4096; i4 += 512) {
        int r = i4 >> 5, c4 = i4 & 31;
        cpa16(Ae + r * 132 + c4 * 4, g_enc_tf + (size_t)(row0 + r) * 128 + c4 * 4);
    }
    CPCOMMIT;
    for (int i = t; i < 1280; i += 512) {
        int r = i / 10, k = i - r * 10;
        sS[r * 12 + k] = g_s[(size_t)(row0 + r) * 10 + k];
    }

    float acc2[2][4];
#pragma unroll
    for (int nf = 0; nf < 2; nf++)
#pragma unroll
        for (int j = 0; j < 4; j++) acc2[nf][j] = 0.f;

    for (int g = 0; g < 5; g++) {
        __syncthreads();
        for (int i4 = t; i4 < 4096; i4 += 512) {
            int e = i4 >> 5, j4 = i4 & 31;
            cpa16(buf2 + e * 136 + j4 * 4,
                  g_we1 + ((size_t)(2 * g + (j4 >> 4)) * 128 + e) * 64 + (j4 & 15) * 4);
        }
        CPCOMMIT;
        if (t < 128) sBe[t] = be1[g * 128 + t];
        for (int i = t; i < 544; i += 512)
            ((uint4*)B2)[i] = ((const uint4*)(g_w2cat + g * 2176))[i];
        CPWAIT0;
        __syncthreads();

        float acc[2][4][4];
#pragma unroll
        for (int m = 0; m < 2; m++)
#pragma unroll
            for (int na = 0; na < 4; na++)
#pragma unroll
                for (int j = 0; j < 4; j++) acc[m][na][j] = 0.f;
#pragma unroll
        for (int ks = 0; ks < 16; ks++) {
            unsigned a[2][4];
#pragma unroll
            for (int m = 0; m < 2; m++) {
                int b = (wm * 32 + 16 * m + gid) * 132 + ks * 8 + q;
                a[m][0] = Ae[b]; a[m][1] = Ae[b + 1056]; a[m][2] = Ae[b + 4]; a[m][3] = Ae[b + 1060];
            }
#pragma unroll
            for (int na = 0; na < 4; na++) {
                int bb = (ks * 8 + q) * 136 + wn * 32 + 8 * na + gid;
                unsigned bh[2] = {buf2[bb], buf2[bb + 544]};
                mma8(acc[0][na], a[0], bh);
                mma8(acc[1][na], a[1], bh);
            }
        }
        __syncthreads();
#pragma unroll
        for (int na = 0; na < 4; na++) {
            int jc = wn * 32 + 8 * na + 2 * q;
            float bia0 = sBe[jc], bia1 = sBe[jc + 1];
            int k0 = 2 * g + (jc >> 6);
#pragma unroll
            for (int m = 0; m < 2; m++) {
                int rr = wm * 32 + 16 * m + gid;
                float s0 = sS[rr * 12 + k0], s1 = sS[(rr + 8) * 12 + k0];
                buf2[rr * 140 + jc]           = f2tf(fmaxf(acc[m][na][0] + bia0, 0.f) * s0);
                buf2[rr * 140 + jc + 1]       = f2tf(fmaxf(acc[m][na][1] + bia1, 0.f) * s0);
                buf2[(rr + 8) * 140 + jc]     = f2tf(fmaxf(acc[m][na][2] + bia0, 0.f) * s1);
                buf2[(rr + 8) * 140 + jc + 1] = f2tf(fmaxf(acc[m][na][3] + bia1, 0.f) * s1);
            }
        }
        for (int i = t; i < 1024; i += 512) {
            int r = i >> 3, jj = 128 + (i & 7);
            float v = (jj == 128) ? sS[r * 12 + 2 * g] : ((jj == 129) ? sS[r * 12 + 2 * g + 1] : 0.f);
            buf2[r * 140 + jj] = f2tf(v);
        }
        __syncthreads();
        if (w < 8) {
#pragma unroll
            for (int ks = 0; ks < 17; ks++) {
                int b = (w * 16 + gid) * 140 + ks * 8 + q;
                unsigned a2[4] = {buf2[b], buf2[b + 1120], buf2[b + 4], buf2[b + 1124]};
#pragma unroll
                for (int nf = 0; nf < 2; nf++) {
                    int bb = (ks * 8 + q) * 16 + nf * 8 + gid;
                    unsigned bh[2] = {B2[bb], B2[bb + 64]};
                    mma8(acc2[nf], a2, bh);
                }
            }
        }
    }
    if (w < 8) {
        size_t r = row0 + w * 16 + gid;
        out[r * 10 + 2 * q]           = acc2[0][0];
        out[r * 10 + 2 * q + 1]       = acc2[0][1];
        out[(r + 8) * 10 + 2 * q]     = acc2[0][2];
        out[(r + 8) * 10 + 2 * q + 1] = acc2[0][3];
        if (q == 0) {
            out[r * 10 + 8] = acc2[1][0];       out[r * 10 + 9] = acc2[1][1];
            out[(r + 8) * 10 + 8] = acc2[1][2]; out[(r + 8) * 10 + 9] = acc2[1][3];
        }
    }
}

// ---------------------------------------------------------------------------
extern "C" void kernel_launch(void* const* d_in, const int* in_sizes, int n_in,
                              void* d_out, int out_size) {
    const float* state = (const float*)d_in[0];
    const float* W1    = (const float*)d_in[1];
    const float* b1    = (const float*)d_in[2];
    const float* gamma = (const float*)d_in[3];
    const float* beta  = (const float*)d_in[4];
    const float* W2    = (const float*)d_in[5];
    const float* b2    = (const float*)d_in[6];
    const float* We1   = (const float*)d_in[7];
    const float* be1   = (const float*)d_in[8];
    const float* We2   = (const float*)d_in[9];
    const float* be2   = (const float*)d_in[10];
    const float* att   = (const float*)d_in[11];
    float* out = (float*)d_out;

    const int SM1 = 52224 * 4, SM2 = 36224 * 4, SMF = 38656 * 4;
    cudaFuncSetAttribute(k_gemm1, cudaFuncAttributeMaxDynamicSharedMemorySize, SM1);
    cudaFuncSetAttribute(k_gemm2, cudaFuncAttributeMaxDynamicSharedMemorySize, SM2);
    cudaFuncSetAttribute(k_fused, cudaFuncAttributeMaxDynamicSharedMemorySize, SMF);

    k_prep <<<256, 256>>>(W1, We1, We2, be2);
    k_gemm1<<<NBLK, 512, SM1>>>(state, b1);
    k_stats<<<256, 256>>>(gamma, beta);
    k_fold <<<128, 256>>>(W2, b2);
    k_gemm2<<<NBLK, 512, SM2>>>(att);
    k_fused<<<NBLK, 512, SMF>>>(be1, out);
}

// round 7
// speedup vs baseline: 1.5928x; 1.1986x over previous
#include <cuda_runtime.h>
#include <cuda_bf16.h>
#include <cuda_fp16.h>
#include <math.h>

#define BTOT 262144
#define NBLK 2048

__device__ unsigned g_hh[(size_t)BTOT * 128];   // h bf16-hi pairs [B][128 pw]
__device__ unsigned g_hl[(size_t)BTOT * 128];   // h bf16-lo pairs
__device__ unsigned g_ench[(size_t)BTOT * 64];  // enc fp16 pairs [B][64 pw]
__device__ float    g_s[(size_t)BTOT * 10];
__device__ float    g_psum[256 * NBLK];
__device__ float    g_psq [256 * NBLK];
__device__ float    g_A[256], g_Bb[256], g_b2p[128];
__device__ unsigned short g_w1h[256 * 128], g_w1l[256 * 128];  // W1 [n][k] bf16
__device__ unsigned short g_w2h[128 * 256], g_w2l[128 * 256];  // W2' [n][k] bf16
__device__ unsigned g_we1p[5 * 128 * 64];   // We1 fp16 pairs [g][j 128][e-pw 64]
__device__ unsigned g_w2c [5 * 16 * 76];    // We2cat fp16 [g][a 16][k-pw 76]

__device__ __forceinline__ void mma16(float* c, const unsigned* a, const unsigned* b) {
    asm volatile("mma.sync.aligned.m16n8k16.row.col.f32.bf16.bf16.f32 "
        "{%0,%1,%2,%3},{%4,%5,%6,%7},{%8,%9},{%0,%1,%2,%3};"
        : "+f"(c[0]), "+f"(c[1]), "+f"(c[2]), "+f"(c[3])
        : "r"(a[0]), "r"(a[1]), "r"(a[2]), "r"(a[3]), "r"(b[0]), "r"(b[1]));
}
__device__ __forceinline__ void mma16h(float* c, const unsigned* a, const unsigned* b) {
    asm volatile("mma.sync.aligned.m16n8k16.row.col.f32.f16.f16.f32 "
        "{%0,%1,%2,%3},{%4,%5,%6,%7},{%8,%9},{%0,%1,%2,%3};"
        : "+f"(c[0]), "+f"(c[1]), "+f"(c[2]), "+f"(c[3])
        : "r"(a[0]), "r"(a[1]), "r"(a[2]), "r"(a[3]), "r"(b[0]), "r"(b[1]));
}
__device__ __forceinline__ unsigned short bh16(float v) {
    __nv_bfloat16 b = __float2bfloat16(v); return *(unsigned short*)&b;
}
__device__ __forceinline__ float bup(unsigned short u) {
    __nv_bfloat16 b = *(__nv_bfloat16*)&u; return __bfloat162float(b);
}
__device__ __forceinline__ void packpair(float v0, float v1, unsigned& hp, unsigned& lp) {
    unsigned short h0 = bh16(v0), h1 = bh16(v1);
    hp = (unsigned)h0 | ((unsigned)h1 << 16);
    lp = (unsigned)bh16(v0 - bup(h0)) | ((unsigned)bh16(v1 - bup(h1)) << 16);
}
__device__ __forceinline__ unsigned packh(float a, float b) {
    __half2 h = __floats2half2_rn(a, b); return *(unsigned*)&h;
}
__device__ __forceinline__ void cpa16(void* dst, const void* src) {
    unsigned d = (unsigned)__cvta_generic_to_shared(dst);
    asm volatile("cp.async.cg.shared.global [%0],[%1],16;\n" :: "r"(d), "l"(src));
}
#define CPCOMMIT asm volatile("cp.async.commit_group;\n")
#define CPWAIT0  asm volatile("cp.async.wait_group 0;\n")

// ------------------- prep -------------------
__global__ void k_prep(const float* __restrict__ W1, const float* __restrict__ We1,
                       const float* __restrict__ We2, const float* __restrict__ be2) {
    int idx = blockIdx.x * blockDim.x + threadIdx.x, st = gridDim.x * blockDim.x;
    for (int i = idx; i < 256 * 128; i += st) {
        int n = i >> 7, k = i & 127;
        float v = (k < 100) ? W1[k * 256 + n] : 0.f;
        unsigned short h = bh16(v);
        g_w1h[i] = h; g_w1l[i] = bh16(v - bup(h));
    }
    for (int i = idx; i < 5 * 128 * 64; i += st) {
        int g = i >> 13, r = i & 8191, j = r >> 6, ep = r & 63;
        int sub = j >> 6, jl = j & 63;
        float v0 = We1[((size_t)(2 * g + sub) * 128 + 2 * ep) * 64 + jl];
        float v1 = We1[((size_t)(2 * g + sub) * 128 + 2 * ep + 1) * 64 + jl];
        g_we1p[i] = packh(v0, v1);
    }
    for (int i = idx; i < 5 * 16 * 76; i += st) {
        int g = i / 1216, r = i - g * 1216, a = r / 76, pw = r - a * 76;
        float v0 = 0.f, v1 = 0.f;
        if (a < 10) {
            if (pw < 64) {
                int j0 = 2 * pw, j1 = 2 * pw + 1;
                v0 = We2[(size_t)((2 * g + (j0 >> 6)) * 64 + (j0 & 63)) * 10 + a];
                v1 = We2[(size_t)((2 * g + (j1 >> 6)) * 64 + (j1 & 63)) * 10 + a];
            } else if (pw == 64) {
                v0 = be2[2 * g * 10 + a]; v1 = be2[(2 * g + 1) * 10 + a];
            }
        }
        g_w2c[i] = packh(v0, v1);
    }
}

// ------- K1: h = relu(state@W1+b1), bf16 3-term, h stored as pair images ----
__global__ __launch_bounds__(512)
void k_gemm1(const float* __restrict__ state, const float* __restrict__ b1) {
    extern __shared__ unsigned sm[];
    unsigned* Ahi = sm;              // [128][68]
    unsigned* Alo = sm + 8704;
    unsigned* Bhi = sm + 17408;      // [256][68]
    unsigned* Blo = sm + 34816;      // end 52224 words
    const int t = threadIdx.x, w = t >> 5, lane = t & 31;
    const int gid = lane >> 2, q = lane & 3;
    const int wm = w >> 2, wn = w & 3, rowb = wm * 32, colb = wn * 64;
    const size_t row0 = (size_t)blockIdx.x * 128;

    for (int i = t; i < 1024; i += 512) {
        int r = i >> 3, sl = i & 7, c0 = sl * 16;
        float vv[16];
#pragma unroll
        for (int u = 0; u < 4; u++) {
            int k = c0 + u * 4;
            float4 x = (k < 100) ? *(const float4*)(state + (row0 + r) * 100 + k)
                                 : make_float4(0.f, 0.f, 0.f, 0.f);
            vv[4 * u] = x.x; vv[4 * u + 1] = x.y; vv[4 * u + 2] = x.z; vv[4 * u + 3] = x.w;
        }
        unsigned H[8], L[8];
#pragma unroll
        for (int u = 0; u < 8; u++) packpair(vv[2 * u], vv[2 * u + 1], H[u], L[u]);
        *(uint4*)(Ahi + r * 68 + sl * 8)     = make_uint4(H[0], H[1], H[2], H[3]);
        *(uint4*)(Ahi + r * 68 + sl * 8 + 4) = make_uint4(H[4], H[5], H[6], H[7]);
        *(uint4*)(Alo + r * 68 + sl * 8)     = make_uint4(L[0], L[1], L[2], L[3]);
        *(uint4*)(Alo + r * 68 + sl * 8 + 4) = make_uint4(L[4], L[5], L[6], L[7]);
    }
    {
        const unsigned* w1hw = (const unsigned*)g_w1h;
        const unsigned* w1lw = (const unsigned*)g_w1l;
        for (int i = t; i < 4096; i += 512) {
            int n = i >> 4, c4 = i & 15;
            *(uint4*)(Bhi + n * 68 + c4 * 4) = *(const uint4*)(w1hw + n * 64 + c4 * 4);
            *(uint4*)(Blo + n * 68 + c4 * 4) = *(const uint4*)(w1lw + n * 64 + c4 * 4);
        }
    }
    __syncthreads();

    float acc[2][8][4];
#pragma unroll
    for (int m = 0; m < 2; m++)
#pragma unroll
        for (int na = 0; na < 8; na++)
#pragma unroll
            for (int j = 0; j < 4; j++) acc[m][na][j] = 0.f;
#pragma unroll
    for (int ks = 0; ks < 8; ks++) {
        unsigned ah[2][4], al[2][4];
#pragma unroll
        for (int m = 0; m < 2; m++) {
            int b = (rowb + 16 * m + gid) * 68 + ks * 8 + q;
            ah[m][0] = Ahi[b]; ah[m][1] = Ahi[b + 544]; ah[m][2] = Ahi[b + 4]; ah[m][3] = Ahi[b + 548];
            al[m][0] = Alo[b]; al[m][1] = Alo[b + 544]; al[m][2] = Alo[b + 4]; al[m][3] = Alo[b + 548];
        }
#pragma unroll
        for (int na = 0; na < 8; na++) {
            int bb = (colb + 8 * na + gid) * 68 + ks * 8 + q;
            unsigned bh[2] = {Bhi[bb], Bhi[bb + 4]};
            unsigned bl[2] = {Blo[bb], Blo[bb + 4]};
#pragma unroll
            for (int m = 0; m < 2; m++) {
                mma16(acc[m][na], ah[m], bh);
                mma16(acc[m][na], al[m], bh);
                mma16(acc[m][na], ah[m], bl);
            }
        }
    }
    __syncthreads();
    float* sums = (float*)sm;     // [4][256]
    float* sqs  = sums + 1024;
#pragma unroll
    for (int na = 0; na < 8; na++) {
        int cg = colb + 8 * na + 2 * q, cg2 = cg >> 1;
        float bias0 = b1[cg], bias1 = b1[cg + 1];
        float p0 = 0.f, p1 = 0.f, q0 = 0.f, q1 = 0.f;
#pragma unroll
        for (int m = 0; m < 2; m++) {
            size_t r = row0 + rowb + 16 * m + gid;
            float v00 = fmaxf(acc[m][na][0] + bias0, 0.f), v01 = fmaxf(acc[m][na][1] + bias1, 0.f);
            float v10 = fmaxf(acc[m][na][2] + bias0, 0.f), v11 = fmaxf(acc[m][na][3] + bias1, 0.f);
            unsigned hp, lp;
            packpair(v00, v01, hp, lp);
            g_hh[r * 128 + cg2] = hp; g_hl[r * 128 + cg2] = lp;
            packpair(v10, v11, hp, lp);
            g_hh[(r + 8) * 128 + cg2] = hp; g_hl[(r + 8) * 128 + cg2] = lp;
            p0 += v00 + v10; p1 += v01 + v11;
            q0 += v00 * v00 + v10 * v10; q1 += v01 * v01 + v11 * v11;
        }
#pragma unroll
        for (int off = 4; off <= 16; off <<= 1) {
            p0 += __shfl_xor_sync(0xffffffffu, p0, off);
            p1 += __shfl_xor_sync(0xffffffffu, p1, off);
            q0 += __shfl_xor_sync(0xffffffffu, q0, off);
            q1 += __shfl_xor_sync(0xffffffffu, q1, off);
        }
        if (gid == 0) {
            sums[wm * 256 + cg] = p0; sums[wm * 256 + cg + 1] = p1;
            sqs [wm * 256 + cg] = q0; sqs [wm * 256 + cg + 1] = q1;
        }
    }
    __syncthreads();
    if (t < 256) {
        float S = sums[t] + sums[256 + t] + sums[512 + t] + sums[768 + t];
        float Q = sqs[t] + sqs[256 + t] + sqs[512 + t] + sqs[768 + t];
        g_psum[t * NBLK + blockIdx.x] = S;
        g_psq [t * NBLK + blockIdx.x] = Q;
    }
}

// ------------------- K2: BN stats finalize -------------------
__global__ __launch_bounds__(256)
void k_stats(const float* __restrict__ gamma, const float* __restrict__ beta) {
    const int c = blockIdx.x, t = threadIdx.x;
    float s = 0.f, qq = 0.f;
    for (int i = t; i < NBLK; i += 256) { s += g_psum[c * NBLK + i]; qq += g_psq[c * NBLK + i]; }
#pragma unroll
    for (int off = 16; off; off >>= 1) {
        s += __shfl_xor_sync(0xffffffffu, s, off);
        qq += __shfl_xor_sync(0xffffffffu, qq, off);
    }
    __shared__ float ss[8], sq[8];
    if ((t & 31) == 0) { ss[t >> 5] = s; sq[t >> 5] = qq; }
    __syncthreads();
    if (t == 0) {
        float S = 0.f, Q = 0.f;
#pragma unroll
        for (int wv = 0; wv < 8; wv++) { S += ss[wv]; Q += sq[wv]; }
        const float inv_n = 1.f / (float)BTOT;
        float mu = S * inv_n;
        float var = Q * inv_n - mu * mu;
        float rstd = rsqrtf(var + 1e-5f);
        float gg = gamma[c];
        g_A[c] = rstd * gg;
        g_Bb[c] = beta[c] - mu * rstd * gg;
    }
}

// ------------- K2b: fold BN into W2 (bf16 split) + b2' ---------------
__global__ __launch_bounds__(256)
void k_fold(const float* __restrict__ W2, const float* __restrict__ b2) {
    const int n = blockIdx.x, k = threadIdx.x;
    float sc = g_A[k] * W2[k * 128 + n];
    unsigned short h = bh16(sc);
    g_w2h[n * 256 + k] = h;
    g_w2l[n * 256 + k] = bh16(sc - bup(h));
    float p = g_Bb[k] * W2[k * 128 + n];
#pragma unroll
    for (int off = 16; off; off >>= 1) p += __shfl_xor_sync(0xffffffffu, p, off);
    __shared__ float red[8];
    if ((k & 31) == 0) red[k >> 5] = p;
    __syncthreads();
    if (k == 0) {
        float S = 0.f;
#pragma unroll
        for (int i = 0; i < 8; i++) S += red[i];
        g_b2p[n] = b2[n] + S;
    }
}

// -- K3: enc = tanh(h@W2'+b2'), bf16 3-term, cp.async A, fused softmax ------
__global__ __launch_bounds__(512)
void k_gemm2(const float* __restrict__ att) {
    extern __shared__ unsigned sm[];
    unsigned* Ahi = sm;              // [128][68]
    unsigned* Alo = sm + 8704;
    unsigned* Bhi = sm + 17408;      // [128][68]
    unsigned* Blo = sm + 26112;      // end 34816
    float* attS = (float*)(sm + 34816);
    float* b2ps = (float*)(sm + 36096);   // end 36224 words
    const int t = threadIdx.x, w = t >> 5, lane = t & 31;
    const int gid = lane >> 2, q = lane & 3;
    const int wm = w >> 2, wn = w & 3, rowb = wm * 32, colb = wn * 32;
    const size_t row0 = (size_t)blockIdx.x * 128;

    for (int i = t; i < 1280; i += 512) attS[i] = att[i];
    if (t < 128) b2ps[t] = g_b2p[t];

    float acc[2][4][4];
#pragma unroll
    for (int m = 0; m < 2; m++)
#pragma unroll
        for (int na = 0; na < 4; na++)
#pragma unroll
            for (int j = 0; j < 4; j++) acc[m][na][j] = 0.f;

    const unsigned* w2hw = (const unsigned*)g_w2h;
    const unsigned* w2lw = (const unsigned*)g_w2l;
    for (int kc = 0; kc < 2; kc++) {
        __syncthreads();
        for (int i = t; i < 2048; i += 512) {
            int r = i >> 4, c4 = i & 15;
            cpa16(Ahi + r * 68 + c4 * 4, g_hh + (row0 + r) * 128 + kc * 64 + c4 * 4);
            cpa16(Alo + r * 68 + c4 * 4, g_hl + (row0 + r) * 128 + kc * 64 + c4 * 4);
        }
        CPCOMMIT;
        for (int i = t; i < 2048; i += 512) {
            int n = i >> 4, c4 = i & 15;
            *(uint4*)(Bhi + n * 68 + c4 * 4) = *(const uint4*)(w2hw + n * 128 + kc * 64 + c4 * 4);
            *(uint4*)(Blo + n * 68 + c4 * 4) = *(const uint4*)(w2lw + n * 128 + kc * 64 + c4 * 4);
        }
        CPWAIT0;
        __syncthreads();
#pragma unroll
        for (int ks = 0; ks < 8; ks++) {
            unsigned ah[2][4], al[2][4];
#pragma unroll
            for (int m = 0; m < 2; m++) {
                int b = (rowb + 16 * m + gid) * 68 + ks * 8 + q;
                ah[m][0] = Ahi[b]; ah[m][1] = Ahi[b + 544]; ah[m][2] = Ahi[b + 4]; ah[m][3] = Ahi[b + 548];
                al[m][0] = Alo[b]; al[m][1] = Alo[b + 544]; al[m][2] = Alo[b + 4]; al[m][3] = Alo[b + 548];
            }
#pragma unroll
            for (int na = 0; na < 4; na++) {
                int bb = (colb + 8 * na + gid) * 68 + ks * 8 + q;
                unsigned bh[2] = {Bhi[bb], Bhi[bb + 4]};
                unsigned bl[2] = {Blo[bb], Blo[bb + 4]};
#pragma unroll
                for (int m = 0; m < 2; m++) {
                    mma16(acc[m][na], ah[m], bh);
                    mma16(acc[m][na], al[m], bh);
                    mma16(acc[m][na], ah[m], bl);
                }
            }
        }
    }
    __syncthreads();
    float* encS = (float*)sm;   // [128][132]
#pragma unroll
    for (int na = 0; na < 4; na++) {
        int cl = colb + 8 * na + 2 * q;
        float bb0 = b2ps[cl], bb1 = b2ps[cl + 1];
#pragma unroll
        for (int m = 0; m < 2; m++) {
            int r = rowb + 16 * m + gid;
            float e00 = tanhf(acc[m][na][0] + bb0), e01 = tanhf(acc[m][na][1] + bb1);
            float e10 = tanhf(acc[m][na][2] + bb0), e11 = tanhf(acc[m][na][3] + bb1);
            encS[r * 132 + cl] = e00;       encS[r * 132 + cl + 1] = e01;
            encS[(r + 8) * 132 + cl] = e10; encS[(r + 8) * 132 + cl + 1] = e11;
            g_ench[(row0 + r) * 64 + (cl >> 1)]     = packh(e00, e01);
            g_ench[(row0 + r + 8) * 64 + (cl >> 1)] = packh(e10, e11);
        }
    }
    __syncthreads();
    for (int it = 0; it < 8; it++) {
        int r = w * 8 + it;
        float4 e4 = *(float4*)(encS + r * 132 + lane * 4);
        float d[10];
#pragma unroll
        for (int k = 0; k < 10; k++) {
            float4 aa = *(float4*)(attS + k * 128 + lane * 4);
            float dx = e4.x - aa.x, dy = e4.y - aa.y, dz = e4.z - aa.z, dw = e4.w - aa.w;
            float p = dx * dx + dy * dy + dz * dz + dw * dw;
#pragma unroll
            for (int off = 16; off; off >>= 1) p += __shfl_xor_sync(0xffffffffu, p, off);
            d[k] = sqrtf(p);
        }
        float dmin = d[0];
#pragma unroll
        for (int k = 1; k < 10; k++) dmin = fminf(dmin, d[k]);
        float s[10], Z = 0.f;
#pragma unroll
        for (int k = 0; k < 10; k++) { s[k] = expf(-2.f * (d[k] - dmin)); Z += s[k]; }
        float invZ = 1.f / Z;
#pragma unroll
        for (int k = 0; k < 10; k++)
            if (lane == k) g_s[(row0 + r) * 10 + k] = s[k] * invZ;
    }
}

// ------------- K4: fused experts (fp16 k16) + gated contraction ------------
__global__ __launch_bounds__(512, 2)
void k_fused(const float* __restrict__ be1, float* __restrict__ out) {
    extern __shared__ unsigned sm[];
    unsigned* Ae  = sm;                  // enc fp16 [128][68]
    unsigned* buf = sm + 8704;           // We1 [128][68] / eh [128][76]
    unsigned* B2  = sm + 18560;          // [16][76]
    float* sS  = (float*)(sm + 19776);   // [128][12]
    float* sBe = (float*)(sm + 21312);   // [128]; total 21440 words
    const int t = threadIdx.x, w = t >> 5, lane = t & 31;
    const int gid = lane >> 2, q = lane & 3;
    const int wm = w >> 2, wn = w & 3;
    const size_t row0 = (size_t)blockIdx.x * 128;

    for (int i = t; i < 2048; i += 512) {
        int r = i >> 4, c4 = i & 15;
        cpa16(Ae + r * 68 + c4 * 4, g_ench + (row0 + r) * 64 + c4 * 4);
    }
    CPCOMMIT;
    for (int i = t; i < 1280; i += 512) {
        int r = i / 10, k = i - r * 10;
        sS[r * 12 + k] = g_s[(row0 + r) * 10 + k];
    }

    float acc2[2][4];
#pragma unroll
    for (int nf = 0; nf < 2; nf++)
#pragma unroll
        for (int j = 0; j < 4; j++) acc2[nf][j] = 0.f;

    for (int g = 0; g < 5; g++) {
        __syncthreads();
        for (int i = t; i < 2048; i += 512) {
            int j = i >> 4, c4 = i & 15;
            cpa16(buf + j * 68 + c4 * 4, g_we1p + g * 8192 + j * 64 + c4 * 4);
        }
        CPCOMMIT;
        if (t < 128) sBe[t] = be1[g * 128 + t];
        for (int i = t; i < 304; i += 512)
            ((uint4*)B2)[i] = ((const uint4*)(g_w2c + g * 1216))[i];
        CPWAIT0;
        __syncthreads();

        float acc[2][4][4];
#pragma unroll
        for (int m = 0; m < 2; m++)
#pragma unroll
            for (int na = 0; na < 4; na++)
#pragma unroll
                for (int j = 0; j < 4; j++) acc[m][na][j] = 0.f;
#pragma unroll
        for (int ks = 0; ks < 8; ks++) {
            unsigned a[2][4];
#pragma unroll
            for (int m = 0; m < 2; m++) {
                int b = (wm * 32 + 16 * m + gid) * 68 + ks * 8 + q;
                a[m][0] = Ae[b]; a[m][1] = Ae[b + 544]; a[m][2] = Ae[b + 4]; a[m][3] = Ae[b + 548];
            }
#pragma unroll
            for (int na = 0; na < 4; na++) {
                int bb = (wn * 32 + 8 * na + gid) * 68 + ks * 8 + q;
                unsigned bh[2] = {buf[bb], buf[bb + 4]};
                mma16h(acc[0][na], a[0], bh);
                mma16h(acc[1][na], a[1], bh);
            }
        }
        __syncthreads();
#pragma unroll
        for (int na = 0; na < 4; na++) {
            int jc = wn * 32 + 8 * na + 2 * q, pw = wn * 16 + 4 * na + q;
            float bia0 = sBe[jc], bia1 = sBe[jc + 1];
            int k0 = 2 * g + (jc >> 6);
#pragma unroll
            for (int m = 0; m < 2; m++) {
                int rr = wm * 32 + 16 * m + gid;
                float s0 = sS[rr * 12 + k0], s1 = sS[(rr + 8) * 12 + k0];
                buf[rr * 76 + pw] = packh(fmaxf(acc[m][na][0] + bia0, 0.f) * s0,
                                          fmaxf(acc[m][na][1] + bia1, 0.f) * s0);
                buf[(rr + 8) * 76 + pw] = packh(fmaxf(acc[m][na][2] + bia0, 0.f) * s1,
                                                fmaxf(acc[m][na][3] + bia1, 0.f) * s1);
            }
        }
        for (int i = t; i < 1024; i += 512) {
            int r = i >> 3, pw = 64 + (i & 7);
            buf[r * 76 + pw] = (pw == 64) ? packh(sS[r * 12 + 2 * g], sS[r * 12 + 2 * g + 1]) : 0u;
        }
        __syncthreads();
        if (w < 8) {
#pragma unroll
            for (int ks = 0; ks < 9; ks++) {
                int b = (w * 16 + gid) * 76 + ks * 8 + q;
                unsigned a2[4] = {buf[b], buf[b + 608], buf[b + 4], buf[b + 612]};
#pragma unroll
                for (int nf = 0; nf < 2; nf++) {
                    int bb = (nf * 8 + gid) * 76 + ks * 8 + q;
                    unsigned bh[2] = {B2[bb], B2[bb + 4]};
                    mma16h(acc2[nf], a2, bh);
                }
            }
        }
    }
    if (w < 8) {
        size_t r = row0 + w * 16 + gid;
        out[r * 10 + 2 * q]           = acc2[0][0];
        out[r * 10 + 2 * q + 1]       = acc2[0][1];
        out[(r + 8) * 10 + 2 * q]     = acc2[0][2];
        out[(r + 8) * 10 + 2 * q + 1] = acc2[0][3];
        if (q == 0) {
            out[r * 10 + 8] = acc2[1][0];       out[r * 10 + 9] = acc2[1][1];
            out[(r + 8) * 10 + 8] = acc2[1][2]; out[(r + 8) * 10 + 9] = acc2[1][3];
        }
    }
}

// ---------------------------------------------------------------------------
extern "C" void kernel_launch(void* const* d_in, const int* in_sizes, int n_in,
                              void* d_out, int out_size) {
    const float* state = (const float*)d_in[0];
    const float* W1    = (const float*)d_in[1];
    const float* b1    = (const float*)d_in[2];
    const float* gamma = (const float*)d_in[3];
    const float* beta  = (const float*)d_in[4];
    const float* W2    = (const float*)d_in[5];
    const float* b2    = (const float*)d_in[6];
    const float* We1   = (const float*)d_in[7];
    const float* be1   = (const float*)d_in[8];
    const float* We2   = (const float*)d_in[9];
    const float* be2   = (const float*)d_in[10];
    const float* att   = (const float*)d_in[11];
    float* out = (float*)d_out;

    const int SM1 = 52224 * 4, SM2 = 36224 * 4, SMF = 21440 * 4;
    cudaFuncSetAttribute(k_gemm1, cudaFuncAttributeMaxDynamicSharedMemorySize, SM1);
    cudaFuncSetAttribute(k_gemm2, cudaFuncAttributeMaxDynamicSharedMemorySize, SM2);
    cudaFuncSetAttribute(k_fused, cudaFuncAttributeMaxDynamicSharedMemorySize, SMF);

    k_prep <<<256, 256>>>(W1, We1, We2, be2);
    k_gemm1<<<NBLK, 512, SM1>>>(state, b1);
    k_stats<<<256, 256>>>(gamma, beta);
    k_fold <<<128, 256>>>(W2, b2);
    k_gemm2<<<NBLK, 512, SM2>>>(att);
    k_fused<<<NBLK, 512, SMF>>>(be1, out);
}